// round 13
// baseline (speedup 1.0000x reference)
#include <cuda_runtime.h>
#include <cuda_fp16.h>
#include <math.h>
#include <stdint.h>

#define NN 20000
#define NE 320000
#define FD 64
#define NH 4
#define HF 256    // NH*FD
#define NGR 64
#define LATD 512
#define GCOLS 832  // FD*(1+3*NH)
#define NBLK ((NN + 255) / 256)   // 79 scan blocks (all co-resident)
#define GEMMB 314 // gemm blocks: ceil(20000/128)*2
#define ENCB 157  // encode blocks: ceil(20000/128)
#define CAP 64    // cached edges per dst in k_agg

// ---------------- scratch (static device globals; no allocs) ----------------
__device__ __half g_n0h[NN * FD];
__device__ __half g_n1h[NN * HF];
__device__ __half g_n2h[NN * HF];
__device__ __half g_n3h[NN * HF];
__device__ __half g_hh [NN * HF];         // fp16 h for aggregation gathers
__device__ float  g_s [NN * NH];
__device__ float  g_d [NN * NH];
__device__ int    g_deg[NN + 1];
__device__ int    g_off[NN + 1];
__device__ int    g_cur[NN];
__device__ int    g_csr[NE];
__device__ int    g_bsum[NBLK + 1];
__device__ int    g_ctrA;
__device__ int    g_gstart[NGR + 1];
__device__ float  g_g[NGR * GCOLS];
__device__ float  g_lat[NGR * LATD];
// fp16 weight copies (converted in k_encode2; consumed by later kernels)
__device__ __half g_w1h[HF * FD];
__device__ __half g_w2h[HF * HF];
__device__ __half g_w3h[HF * HF];

__device__ __forceinline__ float leaky(float x) { return x > 0.f ? x : 0.2f * x; }

__device__ __forceinline__ void cpa16(uint32_t dst, const void* src, bool p) {
    asm volatile("cp.async.ca.shared.global [%0], [%1], 16, %2;"
                 :: "r"(dst), "l"(src), "r"(p ? 16 : 0));
}

// ---------------- encode via tf32 mma + hist + weight fp16 conversion ----------------
__global__ void __launch_bounds__(256) k_encode2(
        const float* __restrict__ sf, const float* __restrict__ bfeat,
        const float* __restrict__ smk, const float* __restrict__ bmk,
        const float* __restrict__ sW, const float* __restrict__ sb,
        const float* __restrict__ bW, const float* __restrict__ bb,
        const float* __restrict__ W1, const float* __restrict__ W2,
        const float* __restrict__ W3,
        const int* __restrict__ ei, int E) {
    extern __shared__ float smem[];
    float* sbs = smem + 13824;
    float* bbs = smem + 13888;
    float* bWs = smem + 13952;
    int tid = threadIdx.x;
    int lane = tid & 31, warp = tid >> 5;
    int warpM = warp >> 1, warpN = warp & 1;
    int bm = blockIdx.x * 128;
    int gid = lane >> 2, tig = lane & 3;
    uint32_t smb = (uint32_t)__cvta_generic_to_shared(smem);

    if (blockIdx.x == 0 && tid == 0) g_ctrA = 0;

    int g = blockIdx.x * 256 + tid;
    int stride = ENCB * 256;
    for (int i = g; i < E; i += stride)
        atomicAdd(&g_deg[ei[E + i]], 1);
    #define CVT_ARR(srcp, dstp, n4)                                        \
        for (int i = g; i < (n4); i += stride) {                           \
            float4 v = ((const float4*)(srcp))[i];                         \
            __half2 h0 = __floats2half2_rn(v.x, v.y);                      \
            __half2 h1 = __floats2half2_rn(v.z, v.w);                      \
            ((uint2*)(dstp))[i] = make_uint2(*(uint32_t*)&h0, *(uint32_t*)&h1); \
        }
    CVT_ARR(W1, g_w1h, HF * 16)
    CVT_ARR(W2, g_w2h, HF * 64)
    CVT_ARR(W3, g_w3h, HF * 64)
    #undef CVT_ARR

    if (tid < 64) { sbs[tid] = sb[tid]; bbs[tid] = bb[tid]; }
    for (int l = tid; l < 320; l += 256) bWs[l] = bW[l];

    float acc[2][4][4];
    #pragma unroll
    for (int mt = 0; mt < 2; mt++)
        #pragma unroll
        for (int nt = 0; nt < 4; nt++)
            #pragma unroll
            for (int j = 0; j < 4; j++) acc[mt][nt][j] = 0.f;

    #define ECOPY(ii, ss) do {                                                   \
        int k0_ = (ii) * 32;                                                     \
        _Pragma("unroll")                                                        \
        for (int l = 0; l < 4; l++) {                                            \
            int idx = tid + 256 * l;                                             \
            int row = idx >> 3, k4 = idx & 7;                                    \
            int gr = bm + row;                                                   \
            bool p = gr < NN;                                                    \
            int grc = p ? gr : (NN - 1);                                         \
            cpa16(smb + ((ss) * 4608 + row * 36 + k4 * 4) * 4,                   \
                  sf + (size_t)grc * 128 + k0_ + k4 * 4, p);                     \
        }                                                                        \
        _Pragma("unroll")                                                        \
        for (int l = 0; l < 2; l++) {                                            \
            int idx = tid + 256 * l;                                             \
            int row = idx >> 3, k4 = idx & 7;                                    \
            cpa16(smb + (9216 + (ss) * 2304 + row * 36 + k4 * 4) * 4,            \
                  sW + (size_t)row * 128 + k0_ + k4 * 4, true);                  \
        }                                                                        \
        asm volatile("cp.async.commit_group;");                                  \
    } while (0)

    ECOPY(0, 0);
    for (int i = 0; i < 4; i++) {
        asm volatile("cp.async.wait_group 0;");
        __syncthreads();
        if (i + 1 < 4) ECOPY(i + 1, (i + 1) & 1);
        const float* As_ = smem + (i & 1) * 4608;
        const float* Bs_ = smem + 9216 + (i & 1) * 2304;
        #pragma unroll
        for (int k8 = 0; k8 < 4; k8++) {
            unsigned a[2][4];
            int col = k8 * 8 + tig;
            #pragma unroll
            for (int mt = 0; mt < 2; mt++) {
                int row = warpM * 32 + mt * 16 + gid;
                a[mt][0] = __float_as_uint(As_[row * 36 + col]);
                a[mt][1] = __float_as_uint(As_[(row + 8) * 36 + col]);
                a[mt][2] = __float_as_uint(As_[row * 36 + col + 4]);
                a[mt][3] = __float_as_uint(As_[(row + 8) * 36 + col + 4]);
            }
            #pragma unroll
            for (int nt = 0; nt < 4; nt++) {
                int colB = warpN * 32 + nt * 8 + gid;
                int rowB = k8 * 8 + tig;
                unsigned b0 = __float_as_uint(Bs_[colB * 36 + rowB]);
                unsigned b1 = __float_as_uint(Bs_[colB * 36 + rowB + 4]);
                #pragma unroll
                for (int mt = 0; mt < 2; mt++) {
                    asm volatile(
                        "mma.sync.aligned.m16n8k8.row.col.f32.tf32.tf32.f32 "
                        "{%0,%1,%2,%3}, {%4,%5,%6,%7}, {%8,%9}, {%0,%1,%2,%3};"
                        : "+f"(acc[mt][nt][0]), "+f"(acc[mt][nt][1]),
                          "+f"(acc[mt][nt][2]), "+f"(acc[mt][nt][3])
                        : "r"(a[mt][0]), "r"(a[mt][1]), "r"(a[mt][2]), "r"(a[mt][3]),
                          "r"(b0), "r"(b1));
                }
            }
        }
        __syncthreads();
    }
    #undef ECOPY

    #pragma unroll
    for (int mt = 0; mt < 2; mt++) {
        int row0 = bm + warpM * 32 + mt * 16 + gid;
        int r1 = row0 + 8;
        int rc0 = (row0 < NN) ? row0 : (NN - 1);
        int rc1 = (r1 < NN) ? r1 : (NN - 1);
        float bf0[5], bf1[5];
        #pragma unroll
        for (int i = 0; i < 5; i++) { bf0[i] = bfeat[rc0 * 5 + i]; bf1[i] = bfeat[rc1 * 5 + i]; }
        float sm0 = smk[rc0], bm0 = bmk[rc0], sm1 = smk[rc1], bm1 = bmk[rc1];
        #pragma unroll
        for (int nt = 0; nt < 4; nt++) {
            int col = warpN * 32 + nt * 8 + tig * 2;
            float o0[2], o1[2];
            #pragma unroll
            for (int c = 0; c < 2; c++) {
                int f = col + c;
                float aS0 = fmaxf(acc[mt][nt][c] + sbs[f], 0.f);
                float aS1 = fmaxf(acc[mt][nt][2 + c] + sbs[f], 0.f);
                float aB0 = bbs[f], aB1 = bbs[f];
                #pragma unroll
                for (int i = 0; i < 5; i++) {
                    aB0 += bf0[i] * bWs[f * 5 + i];
                    aB1 += bf1[i] * bWs[f * 5 + i];
                }
                aB0 = fmaxf(aB0, 0.f); aB1 = fmaxf(aB1, 0.f);
                o0[c] = aS0 * sm0 + aB0 * bm0;
                o1[c] = aS1 * sm1 + aB1 * bm1;
            }
            __half2 h0 = __floats2half2_rn(o0[0], o0[1]);
            __half2 h1 = __floats2half2_rn(o1[0], o1[1]);
            if (row0 < NN) *(__half2*)(g_n0h + (size_t)row0 * FD + col) = h0;
            if (r1 < NN)   *(__half2*)(g_n0h + (size_t)r1 * FD + col)   = h1;
        }
    }
}

// ---------------- scan only (79 co-resident blocks, one spin barrier) ----------------
__global__ void __launch_bounds__(256) k_scan(int E) {
    __shared__ int wsum[8];
    __shared__ int pre_s;
    int b = blockIdx.x, tid = threadIdx.x, lane = tid & 31, w = tid >> 5;
    int i = b * 256 + tid;
    int v = (i < NN) ? g_deg[i] : 0;
    if (i < NN) g_deg[i] = 0;   // reset for next replay
    int x = v;
    #pragma unroll
    for (int o = 1; o < 32; o <<= 1) {
        int y = __shfl_up_sync(0xffffffffu, x, o);
        if (lane >= o) x += y;
    }
    if (lane == 31) wsum[w] = x;
    __syncthreads();
    if (tid < 8) {
        int t2 = wsum[tid];
        #pragma unroll
        for (int o = 1; o < 8; o <<= 1) {
            int y = __shfl_up_sync(0xffu, t2, o);
            if (tid >= o) t2 += y;
        }
        wsum[tid] = t2;
    }
    __syncthreads();
    int excl = x - v + (w > 0 ? wsum[w - 1] : 0);
    if (tid == 255) g_bsum[b] = excl + v;

    __threadfence();
    __syncthreads();
    if (tid == 0) {
        atomicAdd(&g_ctrA, 1);
        while (atomicAdd(&g_ctrA, 0) < NBLK) __nanosleep(32);
        __threadfence();
    }
    __syncthreads();

    if (tid < 32) {
        int s = 0;
        for (int j = tid; j < b; j += 32) s += g_bsum[j];
        #pragma unroll
        for (int o = 16; o; o >>= 1) s += __shfl_xor_sync(0xffffffffu, s, o);
        if (tid == 0) pre_s = s;
    }
    __syncthreads();
    if (i < NN) {
        int o = excl + pre_s;
        g_off[i] = o;
        g_cur[i] = o;
    }
    if (i == 0) g_off[NN] = E;
}

// ---------------- fp16 mma GEMM body (cp.async 2-stage) + fused s/d logits ----------------
__device__ __forceinline__ void gemm_body(__half* smemh,
        const __half* __restrict__ A, const __half* __restrict__ W, int Kdim,
        const float* __restrict__ as_, const float* __restrict__ ad_, int bx) {
    int tid = threadIdx.x;
    int lane = tid & 31, warp = tid >> 5;
    int warpM = warp >> 1, warpN = warp & 1;
    int mi = bx >> 1, ni = bx & 1;
    int bm = mi * 128, bn = ni * 128;
    int gid = lane >> 2, tig = lane & 3;
    uint32_t smb = (uint32_t)__cvta_generic_to_shared(smemh);

    float acc[2][8][4];
    #pragma unroll
    for (int mt = 0; mt < 2; mt++)
        #pragma unroll
        for (int nt = 0; nt < 8; nt++)
            #pragma unroll
            for (int j = 0; j < 4; j++) acc[mt][nt][j] = 0.f;

    int nk = Kdim >> 6;

    #define COPY_STAGE(ii, ss) do {                                              \
        int k0_ = (ii) * 64;                                                     \
        _Pragma("unroll")                                                        \
        for (int l = 0; l < 4; l++) {                                            \
            int idx = tid + 256 * l;                                             \
            int row = idx >> 3, ch = idx & 7;                                    \
            int gr = bm + row;                                                   \
            bool p = gr < NN;                                                    \
            int grc = p ? gr : (NN - 1);                                         \
            cpa16(smb + ((ss) * 9216 + row * 72 + ch * 8) * 2,                   \
                  A + (size_t)grc * Kdim + k0_ + ch * 8, p);                     \
            cpa16(smb + (18432 + (ss) * 9216 + row * 72 + ch * 8) * 2,           \
                  W + (size_t)(bn + row) * Kdim + k0_ + ch * 8, true);           \
        }                                                                        \
        asm volatile("cp.async.commit_group;");                                  \
    } while (0)

    COPY_STAGE(0, 0);

    for (int i = 0; i < nk; i++) {
        asm volatile("cp.async.wait_group 0;");
        __syncthreads();
        if (i + 1 < nk) COPY_STAGE(i + 1, (i + 1) & 1);

        const __half* As_ = smemh + (i & 1) * 9216;
        const __half* Bs_ = smemh + 18432 + (i & 1) * 9216;
        #pragma unroll
        for (int k16 = 0; k16 < 4; k16++) {
            int col = k16 * 16 + tig * 2;
            unsigned a[2][4];
            #pragma unroll
            for (int mt = 0; mt < 2; mt++) {
                int row = warpM * 32 + mt * 16 + gid;
                a[mt][0] = *(const unsigned*)&As_[row * 72 + col];
                a[mt][1] = *(const unsigned*)&As_[(row + 8) * 72 + col];
                a[mt][2] = *(const unsigned*)&As_[row * 72 + col + 8];
                a[mt][3] = *(const unsigned*)&As_[(row + 8) * 72 + col + 8];
            }
            #pragma unroll
            for (int nt = 0; nt < 8; nt++) {
                int colB = warpN * 64 + nt * 8 + gid;
                unsigned b0 = *(const unsigned*)&Bs_[colB * 72 + col];
                unsigned b1 = *(const unsigned*)&Bs_[colB * 72 + col + 8];
                #pragma unroll
                for (int mt = 0; mt < 2; mt++) {
                    asm volatile(
                        "mma.sync.aligned.m16n8k16.row.col.f32.f16.f16.f32 "
                        "{%0,%1,%2,%3}, {%4,%5,%6,%7}, {%8,%9}, {%0,%1,%2,%3};"
                        : "+f"(acc[mt][nt][0]), "+f"(acc[mt][nt][1]),
                          "+f"(acc[mt][nt][2]), "+f"(acc[mt][nt][3])
                        : "r"(a[mt][0]), "r"(a[mt][1]), "r"(a[mt][2]), "r"(a[mt][3]),
                          "r"(b0), "r"(b1));
                }
            }
        }
    }
    #undef COPY_STAGE
    __syncthreads();

    int hd = (bn >> 6) + warpN;
    #pragma unroll
    for (int mt = 0; mt < 2; mt++) {
        int row0 = bm + warpM * 32 + mt * 16 + gid;
        float sp0 = 0.f, sp8 = 0.f, dp0 = 0.f, dp8 = 0.f;
        #pragma unroll
        for (int nt = 0; nt < 8; nt++) {
            int col = bn + warpN * 64 + nt * 8 + tig * 2;
            int lc = nt * 8 + tig * 2;
            float2 a2s = *(const float2*)(as_ + hd * 64 + lc);
            float2 a2d = *(const float2*)(ad_ + hd * 64 + lc);
            sp0 += acc[mt][nt][0] * a2s.x + acc[mt][nt][1] * a2s.y;
            sp8 += acc[mt][nt][2] * a2s.x + acc[mt][nt][3] * a2s.y;
            dp0 += acc[mt][nt][0] * a2d.x + acc[mt][nt][1] * a2d.y;
            dp8 += acc[mt][nt][2] * a2d.x + acc[mt][nt][3] * a2d.y;
            if (row0 < NN)
                *(__half2*)(g_hh + (size_t)row0 * HF + col) =
                    __floats2half2_rn(acc[mt][nt][0], acc[mt][nt][1]);
            if (row0 + 8 < NN)
                *(__half2*)(g_hh + (size_t)(row0 + 8) * HF + col) =
                    __floats2half2_rn(acc[mt][nt][2], acc[mt][nt][3]);
        }
        #pragma unroll
        for (int o = 1; o < 4; o <<= 1) {
            sp0 += __shfl_xor_sync(0xffffffffu, sp0, o);
            sp8 += __shfl_xor_sync(0xffffffffu, sp8, o);
            dp0 += __shfl_xor_sync(0xffffffffu, dp0, o);
            dp8 += __shfl_xor_sync(0xffffffffu, dp8, o);
        }
        if (tig == 0) {
            if (row0 < NN)     { g_s[row0 * NH + hd] = sp0; g_d[row0 * NH + hd] = dp0; }
            if (row0 + 8 < NN) { g_s[(row0 + 8) * NH + hd] = sp8; g_d[(row0 + 8) * NH + hd] = dp8; }
        }
    }
}

__global__ void __launch_bounds__(256, 2) k_gemm(const __half* __restrict__ A,
        const __half* __restrict__ W, int Kdim,
        const float* __restrict__ as_, const float* __restrict__ ad_) {
    extern __shared__ __half smemh[];
    gemm_body(smemh, A, W, Kdim, as_, ad_, blockIdx.x);
}

__global__ void __launch_bounds__(256, 2) k_gemsc(const __half* __restrict__ A,
        const __half* __restrict__ W, int Kdim,
        const float* __restrict__ as_, const float* __restrict__ ad_,
        const int* __restrict__ ei, const int* __restrict__ batch, int E) {
    extern __shared__ __half smemh[];
    if (blockIdx.x < GEMMB) {
        gemm_body(smemh, A, W, Kdim, as_, ad_, blockIdx.x);
        return;
    }
    int i = (blockIdx.x - GEMMB) * 256 + threadIdx.x;
    if (i < E) {
        int dd = ei[E + i];
        int p = atomicAdd(&g_cur[dd], 1);
        g_csr[p] = ei[i];
    }
    if (i == 0) { g_gstart[0] = 0; g_gstart[NGR] = NN; }
    if (i > 0 && i < NN && batch[i] != batch[i - 1]) g_gstart[batch[i]] = i;
}

// ---------------- GAT aggregation: warp per dst; fp16 h rows; 2-edge pipeline; 5 CTA/SM
__global__ void __launch_bounds__(256, 5) k_agg(const float* __restrict__ bias,
                                                __half* __restrict__ xout) {
    __shared__ float4 sle[8][CAP + 1];
    __shared__ int    ssrc[8][CAP + 1];
    int warp = threadIdx.x >> 5, lane = threadIdx.x & 31;
    int dst = blockIdx.x * 8 + warp;
    if (dst >= NN) return;
    int e0 = g_off[dst], e1 = g_off[dst + 1];
    int n = e1 - e0;
    bool cached = (n <= CAP);
    float4 d4 = *(const float4*)(g_d + dst * NH);
    float4 s4self = *(const float4*)(g_s + dst * NH);

    float4 m;
    m.x = leaky(s4self.x + d4.x); m.y = leaky(s4self.y + d4.y);
    m.z = leaky(s4self.z + d4.z); m.w = leaky(s4self.w + d4.w);
    for (int j = lane; j < n; j += 32) {
        int src = g_csr[e0 + j];
        float4 s4 = *(const float4*)(g_s + src * NH);
        float4 le = make_float4(leaky(s4.x + d4.x), leaky(s4.y + d4.y),
                                leaky(s4.z + d4.z), leaky(s4.w + d4.w));
        m.x = fmaxf(m.x, le.x); m.y = fmaxf(m.y, le.y);
        m.z = fmaxf(m.z, le.z); m.w = fmaxf(m.w, le.w);
        if (cached) { ssrc[warp][j] = src; sle[warp][j] = le; }
    }
    #pragma unroll
    for (int o = 16; o; o >>= 1) {
        m.x = fmaxf(m.x, __shfl_xor_sync(0xffffffffu, m.x, o));
        m.y = fmaxf(m.y, __shfl_xor_sync(0xffffffffu, m.y, o));
        m.z = fmaxf(m.z, __shfl_xor_sync(0xffffffffu, m.z, o));
        m.w = fmaxf(m.w, __shfl_xor_sync(0xffffffffu, m.w, o));
    }

    int hd = lane >> 3;
    float mh  = (hd == 0) ? m.x : (hd == 1) ? m.y : (hd == 2) ? m.z : m.w;
    float ddh = (hd == 0) ? d4.x : (hd == 1) ? d4.y : (hd == 2) ? d4.z : d4.w;
    float ssl = (hd == 0) ? s4self.x : (hd == 1) ? s4self.y : (hd == 2) ? s4self.z : s4self.w;

    float den, ac[8];
    {
        float w = __expf(leaky(ssl + ddh) - mh);
        den = w;
        uint4 u = ((const uint4*)(g_hh + (size_t)dst * HF))[lane];
        const __half2* hp = (const __half2*)&u;
        #pragma unroll
        for (int q = 0; q < 4; q++) {
            float2 f = __half22float2(hp[q]);
            ac[q * 2]     = w * f.x;
            ac[q * 2 + 1] = w * f.y;
        }
    }

    if (cached) {
        __syncwarp();
        int j = 0;
        for (; j + 1 < n; j += 2) {
            int s0 = ssrc[warp][j], s1 = ssrc[warp][j + 1];
            uint4 u0 = ((const uint4*)(g_hh + (size_t)s0 * HF))[lane];
            uint4 u1 = ((const uint4*)(g_hh + (size_t)s1 * HF))[lane];
            float4 le0 = sle[warp][j], le1 = sle[warp][j + 1];
            float l0 = (hd == 0) ? le0.x : (hd == 1) ? le0.y : (hd == 2) ? le0.z : le0.w;
            float l1 = (hd == 0) ? le1.x : (hd == 1) ? le1.y : (hd == 2) ? le1.z : le1.w;
            float w0 = __expf(l0 - mh);
            float w1 = __expf(l1 - mh);
            den += w0 + w1;
            const __half2* h0 = (const __half2*)&u0;
            const __half2* h1 = (const __half2*)&u1;
            #pragma unroll
            for (int q = 0; q < 4; q++) {
                float2 f0 = __half22float2(h0[q]);
                float2 f1 = __half22float2(h1[q]);
                ac[q * 2]     += w0 * f0.x + w1 * f1.x;
                ac[q * 2 + 1] += w0 * f0.y + w1 * f1.y;
            }
        }
        if (j < n) {
            int s0 = ssrc[warp][j];
            uint4 u0 = ((const uint4*)(g_hh + (size_t)s0 * HF))[lane];
            float4 le0 = sle[warp][j];
            float l0 = (hd == 0) ? le0.x : (hd == 1) ? le0.y : (hd == 2) ? le0.z : le0.w;
            float w0 = __expf(l0 - mh);
            den += w0;
            const __half2* h0 = (const __half2*)&u0;
            #pragma unroll
            for (int q = 0; q < 4; q++) {
                float2 f0 = __half22float2(h0[q]);
                ac[q * 2]     += w0 * f0.x;
                ac[q * 2 + 1] += w0 * f0.y;
            }
        }
    } else {
        for (int e = e0; e < e1; e++) {
            int src = g_csr[e];
            float4 s4 = *(const float4*)(g_s + src * NH);
            float sh = (hd == 0) ? s4.x : (hd == 1) ? s4.y : (hd == 2) ? s4.z : s4.w;
            float w = __expf(leaky(sh + ddh) - mh);
            den += w;
            uint4 u = ((const uint4*)(g_hh + (size_t)src * HF))[lane];
            const __half2* hp = (const __half2*)&u;
            #pragma unroll
            for (int q = 0; q < 4; q++) {
                float2 f = __half22float2(hp[q]);
                ac[q * 2]     += w * f.x;
                ac[q * 2 + 1] += w * f.y;
            }
        }
    }

    float inv = 1.f / den;
    int c = lane * 8;
    const float4* bp = (const float4*)(bias + c);
    float4 b0 = bp[0], b1 = bp[1];
    __half2 o[4];
    o[0] = __floats2half2_rn(fmaxf(ac[0] * inv + b0.x, 0.f), fmaxf(ac[1] * inv + b0.y, 0.f));
    o[1] = __floats2half2_rn(fmaxf(ac[2] * inv + b0.z, 0.f), fmaxf(ac[3] * inv + b0.w, 0.f));
    o[2] = __floats2half2_rn(fmaxf(ac[4] * inv + b1.x, 0.f), fmaxf(ac[5] * inv + b1.y, 0.f));
    o[3] = __floats2half2_rn(fmaxf(ac[6] * inv + b1.z, 0.f), fmaxf(ac[7] * inv + b1.w, 0.f));
    ((uint4*)(xout + (size_t)dst * HF))[lane] = *(uint4*)o;
}

// ---------------- fused per-graph max pool (fp16 inputs): grid (NGR, 13) ----------------
__global__ void k_poolall() {
    __shared__ float red[4][64];
    int gi = blockIdx.x, seg = blockIdx.y;
    const __half* x; int C, gcol0;
    if (seg == 0)      { x = g_n0h; C = FD; gcol0 = 0; }
    else if (seg <= 4) { x = g_n1h + (seg - 1) * 64; C = HF; gcol0 = FD + (seg - 1) * 64; }
    else if (seg <= 8) { x = g_n2h + (seg - 5) * 64; C = HF; gcol0 = FD + HF + (seg - 5) * 64; }
    else               { x = g_n3h + (seg - 9) * 64; C = HF; gcol0 = FD + 2 * HF + (seg - 9) * 64; }
    int col = threadIdx.x & 63;
    int rg = threadIdx.x >> 6;
    int i0 = g_gstart[gi], i1 = g_gstart[gi + 1];
    float m = -3.0e38f;
    for (int i = i0 + rg; i < i1; i += 4)
        m = fmaxf(m, __half2float(x[(size_t)i * C + col]));
    red[rg][col] = m;
    __syncthreads();
    if (rg == 0) {
        m = fmaxf(fmaxf(red[0][col], red[1][col]), fmaxf(red[2][col], red[3][col]));
        g_g[gi * GCOLS + gcol0 + col] = m;
    }
}

// ---------------- head MLPs ----------------
__global__ void k_latent(const float* __restrict__ W, const float* __restrict__ b) {
    int gi = blockIdx.x;
    int warp = threadIdx.x >> 5, lane = threadIdx.x & 31;
    int j = blockIdx.y * 8 + warp;
    __shared__ float gs[GCOLS];
    for (int i = threadIdx.x; i < GCOLS; i += 256) gs[i] = g_g[gi * GCOLS + i];
    __syncthreads();
    float acc = 0.f;
    for (int k = lane; k < GCOLS; k += 32) acc += gs[k] * W[(size_t)j * GCOLS + k];
    #pragma unroll
    for (int o = 16; o; o >>= 1) acc += __shfl_xor_sync(0xffffffffu, acc, o);
    if (lane == 0) g_lat[gi * LATD + j] = acc + b[j];
}

__global__ void k_head(const float* __restrict__ muW, const float* __restrict__ mub,
                       const float* __restrict__ vW, const float* __restrict__ vb,
                       float* __restrict__ out) {
    int gi = blockIdx.x;
    int warp = threadIdx.x >> 5, lane = threadIdx.x & 31;
    int j = blockIdx.y * 8 + warp;
    __shared__ float ls[LATD];
    for (int i = threadIdx.x; i < LATD; i += 256) ls[i] = g_lat[gi * LATD + i];
    __syncthreads();
    float am = 0.f, av = 0.f;
    for (int k = lane; k < LATD; k += 32) {
        float l = ls[k];
        am += l * muW[(size_t)j * LATD + k];
        av += l * vW[(size_t)j * LATD + k];
    }
    #pragma unroll
    for (int o = 16; o; o >>= 1) {
        am += __shfl_xor_sync(0xffffffffu, am, o);
        av += __shfl_xor_sync(0xffffffffu, av, o);
    }
    if (lane == 0) {
        out[gi * LATD + j] = am + mub[j];
        out[NGR * LATD + gi * LATD + j] = av + vb[j];
    }
}

// ---------------- launch ----------------
extern "C" void kernel_launch(void* const* d_in, const int* in_sizes, int n_in,
                              void* d_out, int out_size) {
    const float* street  = (const float*)d_in[0];
    const float* build   = (const float*)d_in[1];
    const float* smask   = (const float*)d_in[2];
    const float* bmask   = (const float*)d_in[3];
    const int*   ei      = (const int*)d_in[4];
    const int*   batch   = (const int*)d_in[5];
    const float* sW      = (const float*)d_in[6];
    const float* sb      = (const float*)d_in[7];
    const float* bW      = (const float*)d_in[8];
    const float* bb      = (const float*)d_in[9];
    const float* W1      = (const float*)d_in[10];
    const float* as1     = (const float*)d_in[11];
    const float* ad1     = (const float*)d_in[12];
    const float* b1      = (const float*)d_in[13];
    const float* W2      = (const float*)d_in[14];
    const float* as2     = (const float*)d_in[15];
    const float* ad2     = (const float*)d_in[16];
    const float* b2      = (const float*)d_in[17];
    const float* W3      = (const float*)d_in[18];
    const float* as3     = (const float*)d_in[19];
    const float* ad3     = (const float*)d_in[20];
    const float* b3      = (const float*)d_in[21];
    const float* aggW    = (const float*)d_in[22];
    const float* aggb    = (const float*)d_in[23];
    const float* muW     = (const float*)d_in[24];
    const float* mub     = (const float*)d_in[25];
    const float* varW    = (const float*)d_in[26];
    const float* varb    = (const float*)d_in[27];
    float* out = (float*)d_out;

    int E = in_sizes[4] / 2;
    const int GSMEM = 73728;
    const int ESMEM = 14272 * 4;

    static int attr_set = 0;
    if (!attr_set) {
        cudaFuncSetAttribute(k_gemm, cudaFuncAttributeMaxDynamicSharedMemorySize, GSMEM);
        cudaFuncSetAttribute(k_gemsc, cudaFuncAttributeMaxDynamicSharedMemorySize, GSMEM);
        cudaFuncSetAttribute(k_encode2, cudaFuncAttributeMaxDynamicSharedMemorySize, ESMEM);
        attr_set = 1;
    }

    __half *n0h, *n1h, *n2h, *n3h, *w1h, *w2h, *w3h;
    cudaGetSymbolAddress((void**)&n0h, g_n0h);
    cudaGetSymbolAddress((void**)&n1h, g_n1h);
    cudaGetSymbolAddress((void**)&n2h, g_n2h);
    cudaGetSymbolAddress((void**)&n3h, g_n3h);
    cudaGetSymbolAddress((void**)&w1h, g_w1h);
    cudaGetSymbolAddress((void**)&w2h, g_w2h);
    cudaGetSymbolAddress((void**)&w3h, g_w3h);

    int scatB = (E + 255) / 256;

    // 0: encode (tf32 mma) + hist + fp16 weight conversion + counter reset
    k_encode2<<<ENCB, 256, ESMEM>>>(street, build, smask, bmask, sW, sb, bW, bb,
                                    W1, W2, W3, ei, E);
    // 1: scan
    k_scan<<<NBLK, 256>>>(E);
    // 2: layer-1 GEMM (fp16 mma) + scatter + gbounds
    k_gemsc<<<GEMMB + scatB, 256, GSMEM>>>(n0h, w1h, FD, as1, ad1, ei, batch, E);
    // 3: agg L1 (PROFILED LAUNCH)
    k_agg<<<(NN + 7) / 8, 256>>>(b1, n1h);
    // 4-5: layer 2
    k_gemm<<<GEMMB, 256, GSMEM>>>(n1h, w2h, HF, as2, ad2);
    k_agg<<<(NN + 7) / 8, 256>>>(b2, n2h);
    // 6-7: layer 3
    k_gemm<<<GEMMB, 256, GSMEM>>>(n2h, w3h, HF, as3, ad3);
    k_agg<<<(NN + 7) / 8, 256>>>(b3, n3h);
    // 8: pooling
    k_poolall<<<dim3(NGR, 13), 256>>>();
    // 9-10: head
    k_latent<<<dim3(NGR, LATD / 8), 256>>>(aggW, aggb);
    k_head<<<dim3(NGR, LATD / 8), 256>>>(muW, mub, varW, varb, out);
}

// round 14
// speedup vs baseline: 1.4963x; 1.4963x over previous
#include <cuda_runtime.h>
#include <cuda_fp16.h>
#include <math.h>
#include <stdint.h>

#define NN 20000
#define NE 320000
#define FD 64
#define NH 4
#define HF 256    // NH*FD
#define NGR 64
#define LATD 512
#define GCOLS 832  // FD*(1+3*NH)
#define NBLK ((NN + 255) / 256)   // 79 scan blocks (all co-resident)
#define GEMMB 314 // gemm blocks: ceil(20000/128)*2
#define ENCB 157  // encode blocks: ceil(20000/128)
#define CAP 64    // cached edges per dst in k_agg

// ---------------- scratch (static device globals; no allocs) ----------------
__device__ __half g_n0h[NN * FD];
__device__ __half g_n1h[NN * HF];
__device__ __half g_n2h[NN * HF];
__device__ __half g_n3h[NN * HF];
__device__ __half g_hh [NN * HF];         // fp16 h for aggregation gathers
__device__ float  g_s [NN * NH];
__device__ float  g_d [NN * NH];
__device__ int    g_deg[NN + 1];
__device__ int    g_off[NN + 1];
__device__ int    g_cur[NN];
__device__ int    g_csr[NE];
__device__ int    g_bsum[NBLK + 1];
__device__ int    g_ctrA;
__device__ int    g_gstart[NGR + 1];
__device__ float  g_g[NGR * GCOLS];
__device__ float  g_lat[NGR * LATD];
// fp16 weight copies (converted in k_encode2; consumed by later kernels)
__device__ __half g_w1h[HF * FD];
__device__ __half g_w2h[HF * HF];
__device__ __half g_w3h[HF * HF];

__device__ __forceinline__ float leaky(float x) { return x > 0.f ? x : 0.2f * x; }

__device__ __forceinline__ void cpa16(uint32_t dst, const void* src, bool p) {
    asm volatile("cp.async.ca.shared.global [%0], [%1], 16, %2;"
                 :: "r"(dst), "l"(src), "r"(p ? 16 : 0));
}

// ---------------- encode via tf32 mma + hist + weight fp16 conversion ----------------
__global__ void __launch_bounds__(256) k_encode2(
        const float* __restrict__ sf, const float* __restrict__ bfeat,
        const float* __restrict__ smk, const float* __restrict__ bmk,
        const float* __restrict__ sW, const float* __restrict__ sb,
        const float* __restrict__ bW, const float* __restrict__ bb,
        const float* __restrict__ W1, const float* __restrict__ W2,
        const float* __restrict__ W3,
        const int* __restrict__ ei, int E) {
    extern __shared__ float smem[];
    float* sbs = smem + 13824;
    float* bbs = smem + 13888;
    float* bWs = smem + 13952;
    int tid = threadIdx.x;
    int lane = tid & 31, warp = tid >> 5;
    int warpM = warp >> 1, warpN = warp & 1;
    int bm = blockIdx.x * 128;
    int gid = lane >> 2, tig = lane & 3;
    uint32_t smb = (uint32_t)__cvta_generic_to_shared(smem);

    if (blockIdx.x == 0 && tid == 0) g_ctrA = 0;

    int g = blockIdx.x * 256 + tid;
    int stride = ENCB * 256;
    for (int i = g; i < E; i += stride)
        atomicAdd(&g_deg[ei[E + i]], 1);
    #define CVT_ARR(srcp, dstp, n4)                                        \
        for (int i = g; i < (n4); i += stride) {                           \
            float4 v = ((const float4*)(srcp))[i];                         \
            __half2 h0 = __floats2half2_rn(v.x, v.y);                      \
            __half2 h1 = __floats2half2_rn(v.z, v.w);                      \
            ((uint2*)(dstp))[i] = make_uint2(*(uint32_t*)&h0, *(uint32_t*)&h1); \
        }
    CVT_ARR(W1, g_w1h, HF * 16)
    CVT_ARR(W2, g_w2h, HF * 64)
    CVT_ARR(W3, g_w3h, HF * 64)
    #undef CVT_ARR

    if (tid < 64) { sbs[tid] = sb[tid]; bbs[tid] = bb[tid]; }
    for (int l = tid; l < 320; l += 256) bWs[l] = bW[l];

    float acc[2][4][4];
    #pragma unroll
    for (int mt = 0; mt < 2; mt++)
        #pragma unroll
        for (int nt = 0; nt < 4; nt++)
            #pragma unroll
            for (int j = 0; j < 4; j++) acc[mt][nt][j] = 0.f;

    #define ECOPY(ii, ss) do {                                                   \
        int k0_ = (ii) * 32;                                                     \
        _Pragma("unroll")                                                        \
        for (int l = 0; l < 4; l++) {                                            \
            int idx = tid + 256 * l;                                             \
            int row = idx >> 3, k4 = idx & 7;                                    \
            int gr = bm + row;                                                   \
            bool p = gr < NN;                                                    \
            int grc = p ? gr : (NN - 1);                                         \
            cpa16(smb + ((ss) * 4608 + row * 36 + k4 * 4) * 4,                   \
                  sf + (size_t)grc * 128 + k0_ + k4 * 4, p);                     \
        }                                                                        \
        _Pragma("unroll")                                                        \
        for (int l = 0; l < 2; l++) {                                            \
            int idx = tid + 256 * l;                                             \
            int row = idx >> 3, k4 = idx & 7;                                    \
            cpa16(smb + (9216 + (ss) * 2304 + row * 36 + k4 * 4) * 4,            \
                  sW + (size_t)row * 128 + k0_ + k4 * 4, true);                  \
        }                                                                        \
        asm volatile("cp.async.commit_group;");                                  \
    } while (0)

    ECOPY(0, 0);
    for (int i = 0; i < 4; i++) {
        asm volatile("cp.async.wait_group 0;");
        __syncthreads();
        if (i + 1 < 4) ECOPY(i + 1, (i + 1) & 1);
        const float* As_ = smem + (i & 1) * 4608;
        const float* Bs_ = smem + 9216 + (i & 1) * 2304;
        #pragma unroll
        for (int k8 = 0; k8 < 4; k8++) {
            unsigned a[2][4];
            int col = k8 * 8 + tig;
            #pragma unroll
            for (int mt = 0; mt < 2; mt++) {
                int row = warpM * 32 + mt * 16 + gid;
                a[mt][0] = __float_as_uint(As_[row * 36 + col]);
                a[mt][1] = __float_as_uint(As_[(row + 8) * 36 + col]);
                a[mt][2] = __float_as_uint(As_[row * 36 + col + 4]);
                a[mt][3] = __float_as_uint(As_[(row + 8) * 36 + col + 4]);
            }
            #pragma unroll
            for (int nt = 0; nt < 4; nt++) {
                int colB = warpN * 32 + nt * 8 + gid;
                int rowB = k8 * 8 + tig;
                unsigned b0 = __float_as_uint(Bs_[colB * 36 + rowB]);
                unsigned b1 = __float_as_uint(Bs_[colB * 36 + rowB + 4]);
                #pragma unroll
                for (int mt = 0; mt < 2; mt++) {
                    asm volatile(
                        "mma.sync.aligned.m16n8k8.row.col.f32.tf32.tf32.f32 "
                        "{%0,%1,%2,%3}, {%4,%5,%6,%7}, {%8,%9}, {%0,%1,%2,%3};"
                        : "+f"(acc[mt][nt][0]), "+f"(acc[mt][nt][1]),
                          "+f"(acc[mt][nt][2]), "+f"(acc[mt][nt][3])
                        : "r"(a[mt][0]), "r"(a[mt][1]), "r"(a[mt][2]), "r"(a[mt][3]),
                          "r"(b0), "r"(b1));
                }
            }
        }
        __syncthreads();
    }
    #undef ECOPY

    #pragma unroll
    for (int mt = 0; mt < 2; mt++) {
        int row0 = bm + warpM * 32 + mt * 16 + gid;
        int r1 = row0 + 8;
        int rc0 = (row0 < NN) ? row0 : (NN - 1);
        int rc1 = (r1 < NN) ? r1 : (NN - 1);
        float bf0[5], bf1[5];
        #pragma unroll
        for (int i = 0; i < 5; i++) { bf0[i] = bfeat[rc0 * 5 + i]; bf1[i] = bfeat[rc1 * 5 + i]; }
        float sm0 = smk[rc0], bm0 = bmk[rc0], sm1 = smk[rc1], bm1 = bmk[rc1];
        #pragma unroll
        for (int nt = 0; nt < 4; nt++) {
            int col = warpN * 32 + nt * 8 + tig * 2;
            float o0[2], o1[2];
            #pragma unroll
            for (int c = 0; c < 2; c++) {
                int f = col + c;
                float aS0 = fmaxf(acc[mt][nt][c] + sbs[f], 0.f);
                float aS1 = fmaxf(acc[mt][nt][2 + c] + sbs[f], 0.f);
                float aB0 = bbs[f], aB1 = bbs[f];
                #pragma unroll
                for (int i = 0; i < 5; i++) {
                    aB0 += bf0[i] * bWs[f * 5 + i];
                    aB1 += bf1[i] * bWs[f * 5 + i];
                }
                aB0 = fmaxf(aB0, 0.f); aB1 = fmaxf(aB1, 0.f);
                o0[c] = aS0 * sm0 + aB0 * bm0;
                o1[c] = aS1 * sm1 + aB1 * bm1;
            }
            __half2 h0 = __floats2half2_rn(o0[0], o0[1]);
            __half2 h1 = __floats2half2_rn(o1[0], o1[1]);
            if (row0 < NN) *(__half2*)(g_n0h + (size_t)row0 * FD + col) = h0;
            if (r1 < NN)   *(__half2*)(g_n0h + (size_t)r1 * FD + col)   = h1;
        }
    }
}

// ---------------- scan only (79 co-resident blocks, one spin barrier) ----------------
__global__ void __launch_bounds__(256) k_scan(int E) {
    __shared__ int wsum[8];
    __shared__ int pre_s;
    int b = blockIdx.x, tid = threadIdx.x, lane = tid & 31, w = tid >> 5;
    int i = b * 256 + tid;
    int v = (i < NN) ? g_deg[i] : 0;
    if (i < NN) g_deg[i] = 0;   // reset for next replay
    int x = v;
    #pragma unroll
    for (int o = 1; o < 32; o <<= 1) {
        int y = __shfl_up_sync(0xffffffffu, x, o);
        if (lane >= o) x += y;
    }
    if (lane == 31) wsum[w] = x;
    __syncthreads();
    if (tid < 8) {
        int t2 = wsum[tid];
        #pragma unroll
        for (int o = 1; o < 8; o <<= 1) {
            int y = __shfl_up_sync(0xffu, t2, o);
            if (tid >= o) t2 += y;
        }
        wsum[tid] = t2;
    }
    __syncthreads();
    int excl = x - v + (w > 0 ? wsum[w - 1] : 0);
    if (tid == 255) g_bsum[b] = excl + v;

    __threadfence();
    __syncthreads();
    if (tid == 0) {
        atomicAdd(&g_ctrA, 1);
        while (atomicAdd(&g_ctrA, 0) < NBLK) __nanosleep(32);
        __threadfence();
    }
    __syncthreads();

    if (tid < 32) {
        int s = 0;
        for (int j = tid; j < b; j += 32) s += g_bsum[j];
        #pragma unroll
        for (int o = 16; o; o >>= 1) s += __shfl_xor_sync(0xffffffffu, s, o);
        if (tid == 0) pre_s = s;
    }
    __syncthreads();
    if (i < NN) {
        int o = excl + pre_s;
        g_off[i] = o;
        g_cur[i] = o;
    }
    if (i == 0) g_off[NN] = E;
}

// ---------------- fp16 mma GEMM body (cp.async 2-stage) + fused s/d logits ----------------
__device__ __forceinline__ void gemm_body(__half* smemh,
        const __half* __restrict__ A, const __half* __restrict__ W, int Kdim,
        const float* __restrict__ as_, const float* __restrict__ ad_, int bx) {
    int tid = threadIdx.x;
    int lane = tid & 31, warp = tid >> 5;
    int warpM = warp >> 1, warpN = warp & 1;
    int mi = bx >> 1, ni = bx & 1;
    int bm = mi * 128, bn = ni * 128;
    int gid = lane >> 2, tig = lane & 3;
    uint32_t smb = (uint32_t)__cvta_generic_to_shared(smemh);

    float acc[2][8][4];
    #pragma unroll
    for (int mt = 0; mt < 2; mt++)
        #pragma unroll
        for (int nt = 0; nt < 8; nt++)
            #pragma unroll
            for (int j = 0; j < 4; j++) acc[mt][nt][j] = 0.f;

    int nk = Kdim >> 6;

    #define COPY_STAGE(ii, ss) do {                                              \
        int k0_ = (ii) * 64;                                                     \
        _Pragma("unroll")                                                        \
        for (int l = 0; l < 4; l++) {                                            \
            int idx = tid + 256 * l;                                             \
            int row = idx >> 3, ch = idx & 7;                                    \
            int gr = bm + row;                                                   \
            bool p = gr < NN;                                                    \
            int grc = p ? gr : (NN - 1);                                         \
            cpa16(smb + ((ss) * 9216 + row * 72 + ch * 8) * 2,                   \
                  A + (size_t)grc * Kdim + k0_ + ch * 8, p);                     \
            cpa16(smb + (18432 + (ss) * 9216 + row * 72 + ch * 8) * 2,           \
                  W + (size_t)(bn + row) * Kdim + k0_ + ch * 8, true);           \
        }                                                                        \
        asm volatile("cp.async.commit_group;");                                  \
    } while (0)

    COPY_STAGE(0, 0);

    for (int i = 0; i < nk; i++) {
        asm volatile("cp.async.wait_group 0;");
        __syncthreads();
        if (i + 1 < nk) COPY_STAGE(i + 1, (i + 1) & 1);

        const __half* As_ = smemh + (i & 1) * 9216;
        const __half* Bs_ = smemh + 18432 + (i & 1) * 9216;
        #pragma unroll
        for (int k16 = 0; k16 < 4; k16++) {
            int col = k16 * 16 + tig * 2;
            unsigned a[2][4];
            #pragma unroll
            for (int mt = 0; mt < 2; mt++) {
                int row = warpM * 32 + mt * 16 + gid;
                a[mt][0] = *(const unsigned*)&As_[row * 72 + col];
                a[mt][1] = *(const unsigned*)&As_[(row + 8) * 72 + col];
                a[mt][2] = *(const unsigned*)&As_[row * 72 + col + 8];
                a[mt][3] = *(const unsigned*)&As_[(row + 8) * 72 + col + 8];
            }
            #pragma unroll
            for (int nt = 0; nt < 8; nt++) {
                int colB = warpN * 64 + nt * 8 + gid;
                unsigned b0 = *(const unsigned*)&Bs_[colB * 72 + col];
                unsigned b1 = *(const unsigned*)&Bs_[colB * 72 + col + 8];
                #pragma unroll
                for (int mt = 0; mt < 2; mt++) {
                    asm volatile(
                        "mma.sync.aligned.m16n8k16.row.col.f32.f16.f16.f32 "
                        "{%0,%1,%2,%3}, {%4,%5,%6,%7}, {%8,%9}, {%0,%1,%2,%3};"
                        : "+f"(acc[mt][nt][0]), "+f"(acc[mt][nt][1]),
                          "+f"(acc[mt][nt][2]), "+f"(acc[mt][nt][3])
                        : "r"(a[mt][0]), "r"(a[mt][1]), "r"(a[mt][2]), "r"(a[mt][3]),
                          "r"(b0), "r"(b1));
                }
            }
        }
    }
    #undef COPY_STAGE
    __syncthreads();

    int hd = (bn >> 6) + warpN;
    #pragma unroll
    for (int mt = 0; mt < 2; mt++) {
        int row0 = bm + warpM * 32 + mt * 16 + gid;
        float sp0 = 0.f, sp8 = 0.f, dp0 = 0.f, dp8 = 0.f;
        #pragma unroll
        for (int nt = 0; nt < 8; nt++) {
            int col = bn + warpN * 64 + nt * 8 + tig * 2;
            int lc = nt * 8 + tig * 2;
            float2 a2s = *(const float2*)(as_ + hd * 64 + lc);
            float2 a2d = *(const float2*)(ad_ + hd * 64 + lc);
            sp0 += acc[mt][nt][0] * a2s.x + acc[mt][nt][1] * a2s.y;
            sp8 += acc[mt][nt][2] * a2s.x + acc[mt][nt][3] * a2s.y;
            dp0 += acc[mt][nt][0] * a2d.x + acc[mt][nt][1] * a2d.y;
            dp8 += acc[mt][nt][2] * a2d.x + acc[mt][nt][3] * a2d.y;
            if (row0 < NN)
                *(__half2*)(g_hh + (size_t)row0 * HF + col) =
                    __floats2half2_rn(acc[mt][nt][0], acc[mt][nt][1]);
            if (row0 + 8 < NN)
                *(__half2*)(g_hh + (size_t)(row0 + 8) * HF + col) =
                    __floats2half2_rn(acc[mt][nt][2], acc[mt][nt][3]);
        }
        #pragma unroll
        for (int o = 1; o < 4; o <<= 1) {
            sp0 += __shfl_xor_sync(0xffffffffu, sp0, o);
            sp8 += __shfl_xor_sync(0xffffffffu, sp8, o);
            dp0 += __shfl_xor_sync(0xffffffffu, dp0, o);
            dp8 += __shfl_xor_sync(0xffffffffu, dp8, o);
        }
        if (tig == 0) {
            if (row0 < NN)     { g_s[row0 * NH + hd] = sp0; g_d[row0 * NH + hd] = dp0; }
            if (row0 + 8 < NN) { g_s[(row0 + 8) * NH + hd] = sp8; g_d[(row0 + 8) * NH + hd] = dp8; }
        }
    }
}

__global__ void __launch_bounds__(256, 2) k_gemm(const __half* __restrict__ A,
        const __half* __restrict__ W, int Kdim,
        const float* __restrict__ as_, const float* __restrict__ ad_) {
    extern __shared__ __half smemh[];
    gemm_body(smemh, A, W, Kdim, as_, ad_, blockIdx.x);
}

__global__ void __launch_bounds__(256, 2) k_gemsc(const __half* __restrict__ A,
        const __half* __restrict__ W, int Kdim,
        const float* __restrict__ as_, const float* __restrict__ ad_,
        const int* __restrict__ ei, const int* __restrict__ batch, int E) {
    extern __shared__ __half smemh[];
    if (blockIdx.x < GEMMB) {
        gemm_body(smemh, A, W, Kdim, as_, ad_, blockIdx.x);
        return;
    }
    int i = (blockIdx.x - GEMMB) * 256 + threadIdx.x;
    if (i < E) {
        int dd = ei[E + i];
        int p = atomicAdd(&g_cur[dd], 1);
        g_csr[p] = ei[i];
    }
    if (i == 0) { g_gstart[0] = 0; g_gstart[NGR] = NN; }
    if (i > 0 && i < NN && batch[i] != batch[i - 1]) g_gstart[batch[i]] = i;
}

// ---------------- GAT aggregation: warp per dst; fp16 h rows; 2-edge pipeline; 5 CTA/SM
__global__ void __launch_bounds__(256, 5) k_agg(const float* __restrict__ bias,
                                                __half* __restrict__ xout) {
    __shared__ float4 sle[8][CAP + 1];
    __shared__ int    ssrc[8][CAP + 1];
    int warp = threadIdx.x >> 5, lane = threadIdx.x & 31;
    int dst = blockIdx.x * 8 + warp;
    if (dst >= NN) return;
    int e0 = g_off[dst], e1 = g_off[dst + 1];
    int n = e1 - e0;
    bool cached = (n <= CAP);
    float4 d4 = *(const float4*)(g_d + dst * NH);
    float4 s4self = *(const float4*)(g_s + dst * NH);

    float4 m;
    m.x = leaky(s4self.x + d4.x); m.y = leaky(s4self.y + d4.y);
    m.z = leaky(s4self.z + d4.z); m.w = leaky(s4self.w + d4.w);
    for (int j = lane; j < n; j += 32) {
        int src = g_csr[e0 + j];
        float4 s4 = *(const float4*)(g_s + src * NH);
        float4 le = make_float4(leaky(s4.x + d4.x), leaky(s4.y + d4.y),
                                leaky(s4.z + d4.z), leaky(s4.w + d4.w));
        m.x = fmaxf(m.x, le.x); m.y = fmaxf(m.y, le.y);
        m.z = fmaxf(m.z, le.z); m.w = fmaxf(m.w, le.w);
        if (cached) { ssrc[warp][j] = src; sle[warp][j] = le; }
    }
    #pragma unroll
    for (int o = 16; o; o >>= 1) {
        m.x = fmaxf(m.x, __shfl_xor_sync(0xffffffffu, m.x, o));
        m.y = fmaxf(m.y, __shfl_xor_sync(0xffffffffu, m.y, o));
        m.z = fmaxf(m.z, __shfl_xor_sync(0xffffffffu, m.z, o));
        m.w = fmaxf(m.w, __shfl_xor_sync(0xffffffffu, m.w, o));
    }

    int hd = lane >> 3;
    float mh  = (hd == 0) ? m.x : (hd == 1) ? m.y : (hd == 2) ? m.z : m.w;
    float ddh = (hd == 0) ? d4.x : (hd == 1) ? d4.y : (hd == 2) ? d4.z : d4.w;
    float ssl = (hd == 0) ? s4self.x : (hd == 1) ? s4self.y : (hd == 2) ? s4self.z : s4self.w;

    float den, ac[8];
    {
        float w = __expf(leaky(ssl + ddh) - mh);
        den = w;
        uint4 u = ((const uint4*)(g_hh + (size_t)dst * HF))[lane];
        const __half2* hp = (const __half2*)&u;
        #pragma unroll
        for (int q = 0; q < 4; q++) {
            float2 f = __half22float2(hp[q]);
            ac[q * 2]     = w * f.x;
            ac[q * 2 + 1] = w * f.y;
        }
    }

    if (cached) {
        __syncwarp();
        int j = 0;
        for (; j + 1 < n; j += 2) {
            int s0 = ssrc[warp][j], s1 = ssrc[warp][j + 1];
            uint4 u0 = ((const uint4*)(g_hh + (size_t)s0 * HF))[lane];
            uint4 u1 = ((const uint4*)(g_hh + (size_t)s1 * HF))[lane];
            float4 le0 = sle[warp][j], le1 = sle[warp][j + 1];
            float l0 = (hd == 0) ? le0.x : (hd == 1) ? le0.y : (hd == 2) ? le0.z : le0.w;
            float l1 = (hd == 0) ? le1.x : (hd == 1) ? le1.y : (hd == 2) ? le1.z : le1.w;
            float w0 = __expf(l0 - mh);
            float w1 = __expf(l1 - mh);
            den += w0 + w1;
            const __half2* h0 = (const __half2*)&u0;
            const __half2* h1 = (const __half2*)&u1;
            #pragma unroll
            for (int q = 0; q < 4; q++) {
                float2 f0 = __half22float2(h0[q]);
                float2 f1 = __half22float2(h1[q]);
                ac[q * 2]     += w0 * f0.x + w1 * f1.x;
                ac[q * 2 + 1] += w0 * f0.y + w1 * f1.y;
            }
        }
        if (j < n) {
            int s0 = ssrc[warp][j];
            uint4 u0 = ((const uint4*)(g_hh + (size_t)s0 * HF))[lane];
            float4 le0 = sle[warp][j];
            float l0 = (hd == 0) ? le0.x : (hd == 1) ? le0.y : (hd == 2) ? le0.z : le0.w;
            float w0 = __expf(l0 - mh);
            den += w0;
            const __half2* h0 = (const __half2*)&u0;
            #pragma unroll
            for (int q = 0; q < 4; q++) {
                float2 f0 = __half22float2(h0[q]);
                ac[q * 2]     += w0 * f0.x;
                ac[q * 2 + 1] += w0 * f0.y;
            }
        }
    } else {
        for (int e = e0; e < e1; e++) {
            int src = g_csr[e];
            float4 s4 = *(const float4*)(g_s + src * NH);
            float sh = (hd == 0) ? s4.x : (hd == 1) ? s4.y : (hd == 2) ? s4.z : s4.w;
            float w = __expf(leaky(sh + ddh) - mh);
            den += w;
            uint4 u = ((const uint4*)(g_hh + (size_t)src * HF))[lane];
            const __half2* hp = (const __half2*)&u;
            #pragma unroll
            for (int q = 0; q < 4; q++) {
                float2 f = __half22float2(hp[q]);
                ac[q * 2]     += w * f.x;
                ac[q * 2 + 1] += w * f.y;
            }
        }
    }

    float inv = 1.f / den;
    int c = lane * 8;
    const float4* bp = (const float4*)(bias + c);
    float4 b0 = bp[0], b1 = bp[1];
    __half2 o[4];
    o[0] = __floats2half2_rn(fmaxf(ac[0] * inv + b0.x, 0.f), fmaxf(ac[1] * inv + b0.y, 0.f));
    o[1] = __floats2half2_rn(fmaxf(ac[2] * inv + b0.z, 0.f), fmaxf(ac[3] * inv + b0.w, 0.f));
    o[2] = __floats2half2_rn(fmaxf(ac[4] * inv + b1.x, 0.f), fmaxf(ac[5] * inv + b1.y, 0.f));
    o[3] = __floats2half2_rn(fmaxf(ac[6] * inv + b1.z, 0.f), fmaxf(ac[7] * inv + b1.w, 0.f));
    ((uint4*)(xout + (size_t)dst * HF))[lane] = *(uint4*)o;
}

// ---------------- fused per-graph max pool (fp16 inputs): grid (NGR, 13) ----------------
__global__ void k_poolall() {
    __shared__ float red[4][64];
    int gi = blockIdx.x, seg = blockIdx.y;
    const __half* x; int C, gcol0;
    if (seg == 0)      { x = g_n0h; C = FD; gcol0 = 0; }
    else if (seg <= 4) { x = g_n1h + (seg - 1) * 64; C = HF; gcol0 = FD + (seg - 1) * 64; }
    else if (seg <= 8) { x = g_n2h + (seg - 5) * 64; C = HF; gcol0 = FD + HF + (seg - 5) * 64; }
    else               { x = g_n3h + (seg - 9) * 64; C = HF; gcol0 = FD + 2 * HF + (seg - 9) * 64; }
    int col = threadIdx.x & 63;
    int rg = threadIdx.x >> 6;
    int i0 = g_gstart[gi], i1 = g_gstart[gi + 1];
    float m = -3.0e38f;
    for (int i = i0 + rg; i < i1; i += 4)
        m = fmaxf(m, __half2float(x[(size_t)i * C + col]));
    red[rg][col] = m;
    __syncthreads();
    if (rg == 0) {
        m = fmaxf(fmaxf(red[0][col], red[1][col]), fmaxf(red[2][col], red[3][col]));
        g_g[gi * GCOLS + gcol0 + col] = m;
    }
}

// ---------------- head MLPs ----------------
__global__ void k_latent(const float* __restrict__ W, const float* __restrict__ b) {
    int gi = blockIdx.x;
    int warp = threadIdx.x >> 5, lane = threadIdx.x & 31;
    int j = blockIdx.y * 8 + warp;
    __shared__ float gs[GCOLS];
    for (int i = threadIdx.x; i < GCOLS; i += 256) gs[i] = g_g[gi * GCOLS + i];
    __syncthreads();
    float acc = 0.f;
    for (int k = lane; k < GCOLS; k += 32) acc += gs[k] * W[(size_t)j * GCOLS + k];
    #pragma unroll
    for (int o = 16; o; o >>= 1) acc += __shfl_xor_sync(0xffffffffu, acc, o);
    if (lane == 0) g_lat[gi * LATD + j] = acc + b[j];
}

__global__ void k_head(const float* __restrict__ muW, const float* __restrict__ mub,
                       const float* __restrict__ vW, const float* __restrict__ vb,
                       float* __restrict__ out) {
    int gi = blockIdx.x;
    int warp = threadIdx.x >> 5, lane = threadIdx.x & 31;
    int j = blockIdx.y * 8 + warp;
    __shared__ float ls[LATD];
    for (int i = threadIdx.x; i < LATD; i += 256) ls[i] = g_lat[gi * LATD + i];
    __syncthreads();
    float am = 0.f, av = 0.f;
    for (int k = lane; k < LATD; k += 32) {
        float l = ls[k];
        am += l * muW[(size_t)j * LATD + k];
        av += l * vW[(size_t)j * LATD + k];
    }
    #pragma unroll
    for (int o = 16; o; o >>= 1) {
        am += __shfl_xor_sync(0xffffffffu, am, o);
        av += __shfl_xor_sync(0xffffffffu, av, o);
    }
    if (lane == 0) {
        out[gi * LATD + j] = am + mub[j];
        out[NGR * LATD + gi * LATD + j] = av + vb[j];
    }
}

// ---------------- launch ----------------
extern "C" void kernel_launch(void* const* d_in, const int* in_sizes, int n_in,
                              void* d_out, int out_size) {
    const float* street  = (const float*)d_in[0];
    const float* build   = (const float*)d_in[1];
    const float* smask   = (const float*)d_in[2];
    const float* bmask   = (const float*)d_in[3];
    const int*   ei      = (const int*)d_in[4];
    const int*   batch   = (const int*)d_in[5];
    const float* sW      = (const float*)d_in[6];
    const float* sb      = (const float*)d_in[7];
    const float* bW      = (const float*)d_in[8];
    const float* bb      = (const float*)d_in[9];
    const float* W1      = (const float*)d_in[10];
    const float* as1     = (const float*)d_in[11];
    const float* ad1     = (const float*)d_in[12];
    const float* b1      = (const float*)d_in[13];
    const float* W2      = (const float*)d_in[14];
    const float* as2     = (const float*)d_in[15];
    const float* ad2     = (const float*)d_in[16];
    const float* b2      = (const float*)d_in[17];
    const float* W3      = (const float*)d_in[18];
    const float* as3     = (const float*)d_in[19];
    const float* ad3     = (const float*)d_in[20];
    const float* b3      = (const float*)d_in[21];
    const float* aggW    = (const float*)d_in[22];
    const float* aggb    = (const float*)d_in[23];
    const float* muW     = (const float*)d_in[24];
    const float* mub     = (const float*)d_in[25];
    const float* varW    = (const float*)d_in[26];
    const float* varb    = (const float*)d_in[27];
    float* out = (float*)d_out;

    int E = in_sizes[4] / 2;
    const int GSMEM = 73728;
    const int ESMEM = 14272 * 4;

    static int attr_set = 0;
    if (!attr_set) {
        cudaFuncSetAttribute(k_gemm, cudaFuncAttributeMaxDynamicSharedMemorySize, GSMEM);
        cudaFuncSetAttribute(k_gemsc, cudaFuncAttributeMaxDynamicSharedMemorySize, GSMEM);
        cudaFuncSetAttribute(k_encode2, cudaFuncAttributeMaxDynamicSharedMemorySize, ESMEM);
        attr_set = 1;
    }

    __half *n0h, *n1h, *n2h, *n3h, *w1h, *w2h, *w3h;
    cudaGetSymbolAddress((void**)&n0h, g_n0h);
    cudaGetSymbolAddress((void**)&n1h, g_n1h);
    cudaGetSymbolAddress((void**)&n2h, g_n2h);
    cudaGetSymbolAddress((void**)&n3h, g_n3h);
    cudaGetSymbolAddress((void**)&w1h, g_w1h);
    cudaGetSymbolAddress((void**)&w2h, g_w2h);
    cudaGetSymbolAddress((void**)&w3h, g_w3h);

    int scatB = (E + 255) / 256;

    // 0: encode (tf32 mma) + hist + fp16 weight conversion + counter reset
    k_encode2<<<ENCB, 256, ESMEM>>>(street, build, smask, bmask, sW, sb, bW, bb,
                                    W1, W2, W3, ei, E);
    // 1: scan
    k_scan<<<NBLK, 256>>>(E);
    // 2: layer-1 GEMM (fp16 mma) + scatter + gbounds
    k_gemsc<<<GEMMB + scatB, 256, GSMEM>>>(n0h, w1h, FD, as1, ad1, ei, batch, E);
    // 3: agg L1 (PROFILED LAUNCH)
    k_agg<<<(NN + 7) / 8, 256>>>(b1, n1h);
    // 4-5: layer 2
    k_gemm<<<GEMMB, 256, GSMEM>>>(n1h, w2h, HF, as2, ad2);
    k_agg<<<(NN + 7) / 8, 256>>>(b2, n2h);
    // 6-7: layer 3
    k_gemm<<<GEMMB, 256, GSMEM>>>(n2h, w3h, HF, as3, ad3);
    k_agg<<<(NN + 7) / 8, 256>>>(b3, n3h);
    // 8: pooling
    k_poolall<<<dim3(NGR, 13), 256>>>();
    // 9-10: head
    k_latent<<<dim3(NGR, LATD / 8), 256>>>(aggW, aggb);
    k_head<<<dim3(NGR, LATD / 8), 256>>>(muW, mub, varW, varb, out);
}

// round 15
// speedup vs baseline: 1.5738x; 1.0518x over previous
#include <cuda_runtime.h>
#include <cuda_fp16.h>
#include <math.h>
#include <stdint.h>

#define NN 20000
#define NE 320000
#define FD 64
#define NH 4
#define HF 256    // NH*FD
#define NGR 64
#define LATD 512
#define GCOLS 832  // FD*(1+3*NH)
#define NBLK ((NN + 255) / 256)   // 79 scan blocks (all co-resident)
#define GEMMB 314 // gemm blocks: ceil(20000/128)*2
#define ENCB 157  // encode blocks: ceil(20000/128)
#define CAP 64    // cached edges per dst in k_agg

// ---------------- scratch (static device globals; no allocs) ----------------
__device__ __half g_n0h[NN * FD];
__device__ __half g_n1h[NN * HF];
__device__ __half g_n2h[NN * HF];
__device__ __half g_n3h[NN * HF];
__device__ __half g_hh [NN * HF];         // fp16 h for aggregation gathers
__device__ float  g_s [NN * NH];
__device__ float  g_d [NN * NH];
__device__ int    g_deg[NN + 1];
__device__ int    g_off[NN + 1];
__device__ int    g_cur[NN];
__device__ int    g_csr[NE];
__device__ int    g_bsum[NBLK + 1];
__device__ int    g_ctrA;
__device__ int    g_gstart[NGR + 1];
__device__ float  g_g[NGR * GCOLS];
__device__ float  g_lat[NGR * LATD];
// fp16 weight copies (converted in k_encode2; consumed by later kernels)
__device__ __half g_w1h[HF * FD];
__device__ __half g_w2h[HF * HF];
__device__ __half g_w3h[HF * HF];

__device__ __forceinline__ float leaky(float x) { return x > 0.f ? x : 0.2f * x; }

__device__ __forceinline__ void cpa16(uint32_t dst, const void* src, bool p) {
    asm volatile("cp.async.ca.shared.global [%0], [%1], 16, %2;"
                 :: "r"(dst), "l"(src), "r"(p ? 16 : 0));
}

// ---------------- encode via tf32 mma + hist + weight fp16 conversion ----------------
__global__ void __launch_bounds__(256) k_encode2(
        const float* __restrict__ sf, const float* __restrict__ bfeat,
        const float* __restrict__ smk, const float* __restrict__ bmk,
        const float* __restrict__ sW, const float* __restrict__ sb,
        const float* __restrict__ bW, const float* __restrict__ bb,
        const float* __restrict__ W1, const float* __restrict__ W2,
        const float* __restrict__ W3,
        const int* __restrict__ ei, int E) {
    extern __shared__ float smem[];
    float* sbs = smem + 13824;
    float* bbs = smem + 13888;
    float* bWs = smem + 13952;
    int tid = threadIdx.x;
    int lane = tid & 31, warp = tid >> 5;
    int warpM = warp >> 1, warpN = warp & 1;
    int bm = blockIdx.x * 128;
    int gid = lane >> 2, tig = lane & 3;
    uint32_t smb = (uint32_t)__cvta_generic_to_shared(smem);

    if (blockIdx.x == 0 && tid == 0) g_ctrA = 0;

    int g = blockIdx.x * 256 + tid;
    int stride = ENCB * 256;
    for (int i = g; i < E; i += stride)
        atomicAdd(&g_deg[ei[E + i]], 1);
    #define CVT_ARR(srcp, dstp, n4)                                        \
        for (int i = g; i < (n4); i += stride) {                           \
            float4 v = ((const float4*)(srcp))[i];                         \
            __half2 h0 = __floats2half2_rn(v.x, v.y);                      \
            __half2 h1 = __floats2half2_rn(v.z, v.w);                      \
            ((uint2*)(dstp))[i] = make_uint2(*(uint32_t*)&h0, *(uint32_t*)&h1); \
        }
    CVT_ARR(W1, g_w1h, HF * 16)
    CVT_ARR(W2, g_w2h, HF * 64)
    CVT_ARR(W3, g_w3h, HF * 64)
    #undef CVT_ARR

    if (tid < 64) { sbs[tid] = sb[tid]; bbs[tid] = bb[tid]; }
    for (int l = tid; l < 320; l += 256) bWs[l] = bW[l];

    float acc[2][4][4];
    #pragma unroll
    for (int mt = 0; mt < 2; mt++)
        #pragma unroll
        for (int nt = 0; nt < 4; nt++)
            #pragma unroll
            for (int j = 0; j < 4; j++) acc[mt][nt][j] = 0.f;

    #define ECOPY(ii, ss) do {                                                   \
        int k0_ = (ii) * 32;                                                     \
        _Pragma("unroll")                                                        \
        for (int l = 0; l < 4; l++) {                                            \
            int idx = tid + 256 * l;                                             \
            int row = idx >> 3, k4 = idx & 7;                                    \
            int gr = bm + row;                                                   \
            bool p = gr < NN;                                                    \
            int grc = p ? gr : (NN - 1);                                         \
            cpa16(smb + ((ss) * 4608 + row * 36 + k4 * 4) * 4,                   \
                  sf + (size_t)grc * 128 + k0_ + k4 * 4, p);                     \
        }                                                                        \
        _Pragma("unroll")                                                        \
        for (int l = 0; l < 2; l++) {                                            \
            int idx = tid + 256 * l;                                             \
            int row = idx >> 3, k4 = idx & 7;                                    \
            cpa16(smb + (9216 + (ss) * 2304 + row * 36 + k4 * 4) * 4,            \
                  sW + (size_t)row * 128 + k0_ + k4 * 4, true);                  \
        }                                                                        \
        asm volatile("cp.async.commit_group;");                                  \
    } while (0)

    ECOPY(0, 0);
    for (int i = 0; i < 4; i++) {
        asm volatile("cp.async.wait_group 0;");
        __syncthreads();
        if (i + 1 < 4) ECOPY(i + 1, (i + 1) & 1);
        const float* As_ = smem + (i & 1) * 4608;
        const float* Bs_ = smem + 9216 + (i & 1) * 2304;
        #pragma unroll
        for (int k8 = 0; k8 < 4; k8++) {
            unsigned a[2][4];
            int col = k8 * 8 + tig;
            #pragma unroll
            for (int mt = 0; mt < 2; mt++) {
                int row = warpM * 32 + mt * 16 + gid;
                a[mt][0] = __float_as_uint(As_[row * 36 + col]);
                a[mt][1] = __float_as_uint(As_[(row + 8) * 36 + col]);
                a[mt][2] = __float_as_uint(As_[row * 36 + col + 4]);
                a[mt][3] = __float_as_uint(As_[(row + 8) * 36 + col + 4]);
            }
            #pragma unroll
            for (int nt = 0; nt < 4; nt++) {
                int colB = warpN * 32 + nt * 8 + gid;
                int rowB = k8 * 8 + tig;
                unsigned b0 = __float_as_uint(Bs_[colB * 36 + rowB]);
                unsigned b1 = __float_as_uint(Bs_[colB * 36 + rowB + 4]);
                #pragma unroll
                for (int mt = 0; mt < 2; mt++) {
                    asm volatile(
                        "mma.sync.aligned.m16n8k8.row.col.f32.tf32.tf32.f32 "
                        "{%0,%1,%2,%3}, {%4,%5,%6,%7}, {%8,%9}, {%0,%1,%2,%3};"
                        : "+f"(acc[mt][nt][0]), "+f"(acc[mt][nt][1]),
                          "+f"(acc[mt][nt][2]), "+f"(acc[mt][nt][3])
                        : "r"(a[mt][0]), "r"(a[mt][1]), "r"(a[mt][2]), "r"(a[mt][3]),
                          "r"(b0), "r"(b1));
                }
            }
        }
        __syncthreads();
    }
    #undef ECOPY

    #pragma unroll
    for (int mt = 0; mt < 2; mt++) {
        int row0 = bm + warpM * 32 + mt * 16 + gid;
        int r1 = row0 + 8;
        int rc0 = (row0 < NN) ? row0 : (NN - 1);
        int rc1 = (r1 < NN) ? r1 : (NN - 1);
        float bf0[5], bf1[5];
        #pragma unroll
        for (int i = 0; i < 5; i++) { bf0[i] = bfeat[rc0 * 5 + i]; bf1[i] = bfeat[rc1 * 5 + i]; }
        float sm0 = smk[rc0], bm0 = bmk[rc0], sm1 = smk[rc1], bm1 = bmk[rc1];
        #pragma unroll
        for (int nt = 0; nt < 4; nt++) {
            int col = warpN * 32 + nt * 8 + tig * 2;
            float o0[2], o1[2];
            #pragma unroll
            for (int c = 0; c < 2; c++) {
                int f = col + c;
                float aS0 = fmaxf(acc[mt][nt][c] + sbs[f], 0.f);
                float aS1 = fmaxf(acc[mt][nt][2 + c] + sbs[f], 0.f);
                float aB0 = bbs[f], aB1 = bbs[f];
                #pragma unroll
                for (int i = 0; i < 5; i++) {
                    aB0 += bf0[i] * bWs[f * 5 + i];
                    aB1 += bf1[i] * bWs[f * 5 + i];
                }
                aB0 = fmaxf(aB0, 0.f); aB1 = fmaxf(aB1, 0.f);
                o0[c] = aS0 * sm0 + aB0 * bm0;
                o1[c] = aS1 * sm1 + aB1 * bm1;
            }
            __half2 h0 = __floats2half2_rn(o0[0], o0[1]);
            __half2 h1 = __floats2half2_rn(o1[0], o1[1]);
            if (row0 < NN) *(__half2*)(g_n0h + (size_t)row0 * FD + col) = h0;
            if (r1 < NN)   *(__half2*)(g_n0h + (size_t)r1 * FD + col)   = h1;
        }
    }
}

// ---------------- scan only (79 co-resident blocks, one spin barrier) ----------------
__global__ void __launch_bounds__(256) k_scan(int E) {
    __shared__ int wsum[8];
    __shared__ int pre_s;
    int b = blockIdx.x, tid = threadIdx.x, lane = tid & 31, w = tid >> 5;
    int i = b * 256 + tid;
    int v = (i < NN) ? g_deg[i] : 0;
    if (i < NN) g_deg[i] = 0;   // reset for next replay
    int x = v;
    #pragma unroll
    for (int o = 1; o < 32; o <<= 1) {
        int y = __shfl_up_sync(0xffffffffu, x, o);
        if (lane >= o) x += y;
    }
    if (lane == 31) wsum[w] = x;
    __syncthreads();
    if (tid < 8) {
        int t2 = wsum[tid];
        #pragma unroll
        for (int o = 1; o < 8; o <<= 1) {
            int y = __shfl_up_sync(0xffu, t2, o);
            if (tid >= o) t2 += y;
        }
        wsum[tid] = t2;
    }
    __syncthreads();
    int excl = x - v + (w > 0 ? wsum[w - 1] : 0);
    if (tid == 255) g_bsum[b] = excl + v;

    __threadfence();
    __syncthreads();
    if (tid == 0) {
        atomicAdd(&g_ctrA, 1);
        while (atomicAdd(&g_ctrA, 0) < NBLK) __nanosleep(32);
        __threadfence();
    }
    __syncthreads();

    if (tid < 32) {
        int s = 0;
        for (int j = tid; j < b; j += 32) s += g_bsum[j];
        #pragma unroll
        for (int o = 16; o; o >>= 1) s += __shfl_xor_sync(0xffffffffu, s, o);
        if (tid == 0) pre_s = s;
    }
    __syncthreads();
    if (i < NN) {
        int o = excl + pre_s;
        g_off[i] = o;
        g_cur[i] = o;
    }
    if (i == 0) g_off[NN] = E;
}

// ---------------- fp16 mma GEMM body (cp.async 2-stage) + fused s/d logits ----------------
__device__ __forceinline__ void gemm_body(__half* smemh,
        const __half* __restrict__ A, const __half* __restrict__ W, int Kdim,
        const float* __restrict__ as_, const float* __restrict__ ad_, int bx) {
    int tid = threadIdx.x;
    int lane = tid & 31, warp = tid >> 5;
    int warpM = warp >> 1, warpN = warp & 1;
    int mi = bx >> 1, ni = bx & 1;
    int bm = mi * 128, bn = ni * 128;
    int gid = lane >> 2, tig = lane & 3;
    uint32_t smb = (uint32_t)__cvta_generic_to_shared(smemh);

    float acc[2][8][4];
    #pragma unroll
    for (int mt = 0; mt < 2; mt++)
        #pragma unroll
        for (int nt = 0; nt < 8; nt++)
            #pragma unroll
            for (int j = 0; j < 4; j++) acc[mt][nt][j] = 0.f;

    int nk = Kdim >> 6;

    #define COPY_STAGE(ii, ss) do {                                              \
        int k0_ = (ii) * 64;                                                     \
        _Pragma("unroll")                                                        \
        for (int l = 0; l < 4; l++) {                                            \
            int idx = tid + 256 * l;                                             \
            int row = idx >> 3, ch = idx & 7;                                    \
            int gr = bm + row;                                                   \
            bool p = gr < NN;                                                    \
            int grc = p ? gr : (NN - 1);                                         \
            cpa16(smb + ((ss) * 9216 + row * 72 + ch * 8) * 2,                   \
                  A + (size_t)grc * Kdim + k0_ + ch * 8, p);                     \
            cpa16(smb + (18432 + (ss) * 9216 + row * 72 + ch * 8) * 2,           \
                  W + (size_t)(bn + row) * Kdim + k0_ + ch * 8, true);           \
        }                                                                        \
        asm volatile("cp.async.commit_group;");                                  \
    } while (0)

    COPY_STAGE(0, 0);

    for (int i = 0; i < nk; i++) {
        asm volatile("cp.async.wait_group 0;");
        __syncthreads();
        if (i + 1 < nk) COPY_STAGE(i + 1, (i + 1) & 1);

        const __half* As_ = smemh + (i & 1) * 9216;
        const __half* Bs_ = smemh + 18432 + (i & 1) * 9216;
        #pragma unroll
        for (int k16 = 0; k16 < 4; k16++) {
            int col = k16 * 16 + tig * 2;
            unsigned a[2][4];
            #pragma unroll
            for (int mt = 0; mt < 2; mt++) {
                int row = warpM * 32 + mt * 16 + gid;
                a[mt][0] = *(const unsigned*)&As_[row * 72 + col];
                a[mt][1] = *(const unsigned*)&As_[(row + 8) * 72 + col];
                a[mt][2] = *(const unsigned*)&As_[row * 72 + col + 8];
                a[mt][3] = *(const unsigned*)&As_[(row + 8) * 72 + col + 8];
            }
            #pragma unroll
            for (int nt = 0; nt < 8; nt++) {
                int colB = warpN * 64 + nt * 8 + gid;
                unsigned b0 = *(const unsigned*)&Bs_[colB * 72 + col];
                unsigned b1 = *(const unsigned*)&Bs_[colB * 72 + col + 8];
                #pragma unroll
                for (int mt = 0; mt < 2; mt++) {
                    asm volatile(
                        "mma.sync.aligned.m16n8k16.row.col.f32.f16.f16.f32 "
                        "{%0,%1,%2,%3}, {%4,%5,%6,%7}, {%8,%9}, {%0,%1,%2,%3};"
                        : "+f"(acc[mt][nt][0]), "+f"(acc[mt][nt][1]),
                          "+f"(acc[mt][nt][2]), "+f"(acc[mt][nt][3])
                        : "r"(a[mt][0]), "r"(a[mt][1]), "r"(a[mt][2]), "r"(a[mt][3]),
                          "r"(b0), "r"(b1));
                }
            }
        }
    }
    #undef COPY_STAGE
    __syncthreads();

    int hd = (bn >> 6) + warpN;
    #pragma unroll
    for (int mt = 0; mt < 2; mt++) {
        int row0 = bm + warpM * 32 + mt * 16 + gid;
        float sp0 = 0.f, sp8 = 0.f, dp0 = 0.f, dp8 = 0.f;
        #pragma unroll
        for (int nt = 0; nt < 8; nt++) {
            int col = bn + warpN * 64 + nt * 8 + tig * 2;
            int lc = nt * 8 + tig * 2;
            float2 a2s = *(const float2*)(as_ + hd * 64 + lc);
            float2 a2d = *(const float2*)(ad_ + hd * 64 + lc);
            sp0 += acc[mt][nt][0] * a2s.x + acc[mt][nt][1] * a2s.y;
            sp8 += acc[mt][nt][2] * a2s.x + acc[mt][nt][3] * a2s.y;
            dp0 += acc[mt][nt][0] * a2d.x + acc[mt][nt][1] * a2d.y;
            dp8 += acc[mt][nt][2] * a2d.x + acc[mt][nt][3] * a2d.y;
            if (row0 < NN)
                *(__half2*)(g_hh + (size_t)row0 * HF + col) =
                    __floats2half2_rn(acc[mt][nt][0], acc[mt][nt][1]);
            if (row0 + 8 < NN)
                *(__half2*)(g_hh + (size_t)(row0 + 8) * HF + col) =
                    __floats2half2_rn(acc[mt][nt][2], acc[mt][nt][3]);
        }
        #pragma unroll
        for (int o = 1; o < 4; o <<= 1) {
            sp0 += __shfl_xor_sync(0xffffffffu, sp0, o);
            sp8 += __shfl_xor_sync(0xffffffffu, sp8, o);
            dp0 += __shfl_xor_sync(0xffffffffu, dp0, o);
            dp8 += __shfl_xor_sync(0xffffffffu, dp8, o);
        }
        if (tig == 0) {
            if (row0 < NN)     { g_s[row0 * NH + hd] = sp0; g_d[row0 * NH + hd] = dp0; }
            if (row0 + 8 < NN) { g_s[(row0 + 8) * NH + hd] = sp8; g_d[(row0 + 8) * NH + hd] = dp8; }
        }
    }
}

__global__ void __launch_bounds__(256, 2) k_gemm(const __half* __restrict__ A,
        const __half* __restrict__ W, int Kdim,
        const float* __restrict__ as_, const float* __restrict__ ad_) {
    extern __shared__ __half smemh[];
    gemm_body(smemh, A, W, Kdim, as_, ad_, blockIdx.x);
}

__global__ void __launch_bounds__(256, 2) k_gemsc(const __half* __restrict__ A,
        const __half* __restrict__ W, int Kdim,
        const float* __restrict__ as_, const float* __restrict__ ad_,
        const int* __restrict__ ei, const int* __restrict__ batch, int E) {
    extern __shared__ __half smemh[];
    if (blockIdx.x < GEMMB) {
        gemm_body(smemh, A, W, Kdim, as_, ad_, blockIdx.x);
        return;
    }
    int i = (blockIdx.x - GEMMB) * 256 + threadIdx.x;
    if (i < E) {
        int dd = ei[E + i];
        int p = atomicAdd(&g_cur[dd], 1);
        g_csr[p] = ei[i];
    }
    if (i == 0) { g_gstart[0] = 0; g_gstart[NGR] = NN; }
    if (i > 0 && i < NN && batch[i] != batch[i - 1]) g_gstart[batch[i]] = i;
}

// ---------------- GAT aggregation: warp per dst; fp16 h rows; HFMA2 block accum
// lane l owns feats 8l..8l+7 (head l>>3); logits cached transposed per head
__global__ void __launch_bounds__(256, 5) k_agg(const float* __restrict__ bias,
                                                __half* __restrict__ xout) {
    __shared__ float sle[8][NH][CAP + 1];
    __shared__ int   ssrc[8][CAP + 1];
    int warp = threadIdx.x >> 5, lane = threadIdx.x & 31;
    int dst = blockIdx.x * 8 + warp;
    if (dst >= NN) return;
    int e0 = g_off[dst], e1 = g_off[dst + 1];
    int n = e1 - e0;
    bool cached = (n <= CAP);
    float4 d4 = *(const float4*)(g_d + dst * NH);
    float4 s4self = *(const float4*)(g_s + dst * NH);

    // pass 1: per-head max + cache (src, transposed leaky logits)
    float4 m;
    m.x = leaky(s4self.x + d4.x); m.y = leaky(s4self.y + d4.y);
    m.z = leaky(s4self.z + d4.z); m.w = leaky(s4self.w + d4.w);
    for (int j = lane; j < n; j += 32) {
        int src = g_csr[e0 + j];
        float4 s4 = *(const float4*)(g_s + src * NH);
        float4 le = make_float4(leaky(s4.x + d4.x), leaky(s4.y + d4.y),
                                leaky(s4.z + d4.z), leaky(s4.w + d4.w));
        m.x = fmaxf(m.x, le.x); m.y = fmaxf(m.y, le.y);
        m.z = fmaxf(m.z, le.z); m.w = fmaxf(m.w, le.w);
        if (cached) {
            ssrc[warp][j] = src;
            sle[warp][0][j] = le.x;
            sle[warp][1][j] = le.y;
            sle[warp][2][j] = le.z;
            sle[warp][3][j] = le.w;
        }
    }
    #pragma unroll
    for (int o = 16; o; o >>= 1) {
        m.x = fmaxf(m.x, __shfl_xor_sync(0xffffffffu, m.x, o));
        m.y = fmaxf(m.y, __shfl_xor_sync(0xffffffffu, m.y, o));
        m.z = fmaxf(m.z, __shfl_xor_sync(0xffffffffu, m.z, o));
        m.w = fmaxf(m.w, __shfl_xor_sync(0xffffffffu, m.w, o));
    }

    int hd = lane >> 3;
    float mh  = (hd == 0) ? m.x : (hd == 1) ? m.y : (hd == 2) ? m.z : m.w;
    float ddh = (hd == 0) ? d4.x : (hd == 1) ? d4.y : (hd == 2) ? d4.z : d4.w;
    float ssl = (hd == 0) ? s4self.x : (hd == 1) ? s4self.y : (hd == 2) ? s4self.z : s4self.w;

    // self contribution (fp32 path)
    float den, ac[8];
    {
        float w = __expf(leaky(ssl + ddh) - mh);
        den = w;
        uint4 u = ((const uint4*)(g_hh + (size_t)dst * HF))[lane];
        const __half2* hp = (const __half2*)&u;
        #pragma unroll
        for (int q = 0; q < 4; q++) {
            float2 f = __half22float2(hp[q]);
            ac[q * 2]     = w * f.x;
            ac[q * 2 + 1] = w * f.y;
        }
    }

    if (cached) {
        __syncwarp();
        const float* lerow = sle[warp][hd];
        // blocks of 8 edges accumulated in half2, flushed to fp32
        for (int jb = 0; jb < n; jb += 8) {
            int je = (jb + 8 < n) ? jb + 8 : n;
            __half2 ah[4];
            ah[0] = ah[1] = ah[2] = ah[3] = __float2half2_rn(0.f);
            #pragma unroll 2
            for (int j = jb; j < je; j++) {
                int src = ssrc[warp][j];
                uint4 u = ((const uint4*)(g_hh + (size_t)src * HF))[lane];
                float w = __expf(lerow[j] - mh);
                den += w;
                __half2 wh = __half2half2(__float2half_rn(w));
                const __half2* hp = (const __half2*)&u;
                ah[0] = __hfma2(wh, hp[0], ah[0]);
                ah[1] = __hfma2(wh, hp[1], ah[1]);
                ah[2] = __hfma2(wh, hp[2], ah[2]);
                ah[3] = __hfma2(wh, hp[3], ah[3]);
            }
            #pragma unroll
            for (int q = 0; q < 4; q++) {
                float2 f = __half22float2(ah[q]);
                ac[q * 2]     += f.x;
                ac[q * 2 + 1] += f.y;
            }
        }
    } else {
        for (int e = e0; e < e1; e++) {
            int src = g_csr[e];
            float4 s4 = *(const float4*)(g_s + src * NH);
            float sh = (hd == 0) ? s4.x : (hd == 1) ? s4.y : (hd == 2) ? s4.z : s4.w;
            float w = __expf(leaky(sh + ddh) - mh);
            den += w;
            uint4 u = ((const uint4*)(g_hh + (size_t)src * HF))[lane];
            const __half2* hp = (const __half2*)&u;
            #pragma unroll
            for (int q = 0; q < 4; q++) {
                float2 f = __half22float2(hp[q]);
                ac[q * 2]     += w * f.x;
                ac[q * 2 + 1] += w * f.y;
            }
        }
    }

    float inv = 1.f / den;
    int c = lane * 8;
    const float4* bp = (const float4*)(bias + c);
    float4 b0 = bp[0], b1 = bp[1];
    __half2 o[4];
    o[0] = __floats2half2_rn(fmaxf(ac[0] * inv + b0.x, 0.f), fmaxf(ac[1] * inv + b0.y, 0.f));
    o[1] = __floats2half2_rn(fmaxf(ac[2] * inv + b0.z, 0.f), fmaxf(ac[3] * inv + b0.w, 0.f));
    o[2] = __floats2half2_rn(fmaxf(ac[4] * inv + b1.x, 0.f), fmaxf(ac[5] * inv + b1.y, 0.f));
    o[3] = __floats2half2_rn(fmaxf(ac[6] * inv + b1.z, 0.f), fmaxf(ac[7] * inv + b1.w, 0.f));
    ((uint4*)(xout + (size_t)dst * HF))[lane] = *(uint4*)o;
}

// ---------------- fused per-graph max pool (fp16 inputs): grid (NGR, 13) ----------------
__global__ void k_poolall() {
    __shared__ float red[4][64];
    int gi = blockIdx.x, seg = blockIdx.y;
    const __half* x; int C, gcol0;
    if (seg == 0)      { x = g_n0h; C = FD; gcol0 = 0; }
    else if (seg <= 4) { x = g_n1h + (seg - 1) * 64; C = HF; gcol0 = FD + (seg - 1) * 64; }
    else if (seg <= 8) { x = g_n2h + (seg - 5) * 64; C = HF; gcol0 = FD + HF + (seg - 5) * 64; }
    else               { x = g_n3h + (seg - 9) * 64; C = HF; gcol0 = FD + 2 * HF + (seg - 9) * 64; }
    int col = threadIdx.x & 63;
    int rg = threadIdx.x >> 6;
    int i0 = g_gstart[gi], i1 = g_gstart[gi + 1];
    float m = -3.0e38f;
    for (int i = i0 + rg; i < i1; i += 4)
        m = fmaxf(m, __half2float(x[(size_t)i * C + col]));
    red[rg][col] = m;
    __syncthreads();
    if (rg == 0) {
        m = fmaxf(fmaxf(red[0][col], red[1][col]), fmaxf(red[2][col], red[3][col]));
        g_g[gi * GCOLS + gcol0 + col] = m;
    }
}

// ---------------- head MLPs ----------------
__global__ void k_latent(const float* __restrict__ W, const float* __restrict__ b) {
    int gi = blockIdx.x;
    int warp = threadIdx.x >> 5, lane = threadIdx.x & 31;
    int j = blockIdx.y * 8 + warp;
    __shared__ float gs[GCOLS];
    for (int i = threadIdx.x; i < GCOLS; i += 256) gs[i] = g_g[gi * GCOLS + i];
    __syncthreads();
    float acc = 0.f;
    for (int k = lane; k < GCOLS; k += 32) acc += gs[k] * W[(size_t)j * GCOLS + k];
    #pragma unroll
    for (int o = 16; o; o >>= 1) acc += __shfl_xor_sync(0xffffffffu, acc, o);
    if (lane == 0) g_lat[gi * LATD + j] = acc + b[j];
}

__global__ void k_head(const float* __restrict__ muW, const float* __restrict__ mub,
                       const float* __restrict__ vW, const float* __restrict__ vb,
                       float* __restrict__ out) {
    int gi = blockIdx.x;
    int warp = threadIdx.x >> 5, lane = threadIdx.x & 31;
    int j = blockIdx.y * 8 + warp;
    __shared__ float ls[LATD];
    for (int i = threadIdx.x; i < LATD; i += 256) ls[i] = g_lat[gi * LATD + i];
    __syncthreads();
    float am = 0.f, av = 0.f;
    for (int k = lane; k < LATD; k += 32) {
        float l = ls[k];
        am += l * muW[(size_t)j * LATD + k];
        av += l * vW[(size_t)j * LATD + k];
    }
    #pragma unroll
    for (int o = 16; o; o >>= 1) {
        am += __shfl_xor_sync(0xffffffffu, am, o);
        av += __shfl_xor_sync(0xffffffffu, av, o);
    }
    if (lane == 0) {
        out[gi * LATD + j] = am + mub[j];
        out[NGR * LATD + gi * LATD + j] = av + vb[j];
    }
}

// ---------------- launch ----------------
extern "C" void kernel_launch(void* const* d_in, const int* in_sizes, int n_in,
                              void* d_out, int out_size) {
    const float* street  = (const float*)d_in[0];
    const float* build   = (const float*)d_in[1];
    const float* smask   = (const float*)d_in[2];
    const float* bmask   = (const float*)d_in[3];
    const int*   ei      = (const int*)d_in[4];
    const int*   batch   = (const int*)d_in[5];
    const float* sW      = (const float*)d_in[6];
    const float* sb      = (const float*)d_in[7];
    const float* bW      = (const float*)d_in[8];
    const float* bb      = (const float*)d_in[9];
    const float* W1      = (const float*)d_in[10];
    const float* as1     = (const float*)d_in[11];
    const float* ad1     = (const float*)d_in[12];
    const float* b1      = (const float*)d_in[13];
    const float* W2      = (const float*)d_in[14];
    const float* as2     = (const float*)d_in[15];
    const float* ad2     = (const float*)d_in[16];
    const float* b2      = (const float*)d_in[17];
    const float* W3      = (const float*)d_in[18];
    const float* as3     = (const float*)d_in[19];
    const float* ad3     = (const float*)d_in[20];
    const float* b3      = (const float*)d_in[21];
    const float* aggW    = (const float*)d_in[22];
    const float* aggb    = (const float*)d_in[23];
    const float* muW     = (const float*)d_in[24];
    const float* mub     = (const float*)d_in[25];
    const float* varW    = (const float*)d_in[26];
    const float* varb    = (const float*)d_in[27];
    float* out = (float*)d_out;

    int E = in_sizes[4] / 2;
    const int GSMEM = 73728;
    const int ESMEM = 14272 * 4;

    static int attr_set = 0;
    if (!attr_set) {
        cudaFuncSetAttribute(k_gemm, cudaFuncAttributeMaxDynamicSharedMemorySize, GSMEM);
        cudaFuncSetAttribute(k_gemsc, cudaFuncAttributeMaxDynamicSharedMemorySize, GSMEM);
        cudaFuncSetAttribute(k_encode2, cudaFuncAttributeMaxDynamicSharedMemorySize, ESMEM);
        attr_set = 1;
    }

    __half *n0h, *n1h, *n2h, *n3h, *w1h, *w2h, *w3h;
    cudaGetSymbolAddress((void**)&n0h, g_n0h);
    cudaGetSymbolAddress((void**)&n1h, g_n1h);
    cudaGetSymbolAddress((void**)&n2h, g_n2h);
    cudaGetSymbolAddress((void**)&n3h, g_n3h);
    cudaGetSymbolAddress((void**)&w1h, g_w1h);
    cudaGetSymbolAddress((void**)&w2h, g_w2h);
    cudaGetSymbolAddress((void**)&w3h, g_w3h);

    int scatB = (E + 255) / 256;

    // 0: encode (tf32 mma) + hist + fp16 weight conversion + counter reset
    k_encode2<<<ENCB, 256, ESMEM>>>(street, build, smask, bmask, sW, sb, bW, bb,
                                    W1, W2, W3, ei, E);
    // 1: scan
    k_scan<<<NBLK, 256>>>(E);
    // 2: layer-1 GEMM (fp16 mma) + scatter + gbounds
    k_gemsc<<<GEMMB + scatB, 256, GSMEM>>>(n0h, w1h, FD, as1, ad1, ei, batch, E);
    // 3: agg L1 (PROFILED LAUNCH)
    k_agg<<<(NN + 7) / 8, 256>>>(b1, n1h);
    // 4-5: layer 2
    k_gemm<<<GEMMB, 256, GSMEM>>>(n1h, w2h, HF, as2, ad2);
    k_agg<<<(NN + 7) / 8, 256>>>(b2, n2h);
    // 6-7: layer 3
    k_gemm<<<GEMMB, 256, GSMEM>>>(n2h, w3h, HF, as3, ad3);
    k_agg<<<(NN + 7) / 8, 256>>>(b3, n3h);
    // 8: pooling
    k_poolall<<<dim3(NGR, 13), 256>>>();
    // 9-10: head
    k_latent<<<dim3(NGR, LATD / 8), 256>>>(aggW, aggb);
    k_head<<<dim3(NGR, LATD / 8), 256>>>(muW, mub, varW, varb, out);
}